// round 13
// baseline (speedup 1.0000x reference)
#include <cuda_runtime.h>
#include <cstdint>
#include <math.h>

#define BB 4
#define CC 256
#define NPTS 16384
#define MTOT 65536
#define HC 64
#define NOUT 320
#define NQ 256
#define NS0 32
#define NS1 64

#define OFF_QUERY 0
#define OFF_QF    3072
#define OFF_PRED  265216
#define OFF_M     265256
#define OFF_G0    17042472
#define OFF_G1    17075240

__device__ float g_W[CC * NOUT];
__device__ float g_Y[HC * MTOT];    // column-major [col][m]  (for kq/khpart)
__device__ float g_Yt[MTOT * HC];   // row-major [m][col]     (for exact stats)
__device__ float g_mean[NOUT];
__device__ float g_rstd[NOUT];
__device__ float g_hpart[256 * HC];
__device__ int   g_label[BB];
__device__ float g_qval[MTOT];
__device__ float g_exp[MTOT];
__device__ unsigned long long g_keys[MTOT];
__device__ float g_max[BB];
__device__ float g_lse[BB];
__device__ int   g_qidx[BB * NQ];
__device__ float g_sink;

// ---------- fast gelu (1e-3-tolerance outputs only) ----------
__device__ __forceinline__ float gelu_fast(float x) {
    float x3 = x * x * x;
    float t = tanhf(0.7978845608028654f * (x + 0.044715f * x3));
    return 0.5f * x * (1.0f + t);
}

// ---------- XLA FastTanh (rational, separate mul/add, fdiv) ----------
__device__ __forceinline__ float xla_tanhf(float x) {
    if (fabsf(x) < 0.0004f) return x;
    float xc = fminf(fmaxf(x, -7.90531110763549805f), 7.90531110763549805f);
    float x2 = __fmul_rn(xc, xc);
    float p = -2.76076847742355e-16f;
    p = __fadd_rn(__fmul_rn(p, x2), 2.00018790482477e-13f);
    p = __fadd_rn(__fmul_rn(p, x2), -8.60467152213735e-11f);
    p = __fadd_rn(__fmul_rn(p, x2), 5.12229709037114e-08f);
    p = __fadd_rn(__fmul_rn(p, x2), 1.48572235717979e-05f);
    p = __fadd_rn(__fmul_rn(p, x2), 6.37261928875436e-04f);
    p = __fadd_rn(__fmul_rn(p, x2), 4.89352455891786e-03f);
    float num = __fmul_rn(xc, p);
    float q = 1.19825839466702e-06f;
    q = __fadd_rn(__fmul_rn(q, x2), 1.18534705686654e-04f);
    q = __fadd_rn(__fmul_rn(q, x2), 2.26843463243900e-03f);
    q = __fadd_rn(__fmul_rn(q, x2), 4.89352518554385e-03f);
    return __fdiv_rn(num, q);
}

__device__ __forceinline__ float gelu_exact(float x) {
    float x2 = __fmul_rn(x, x);
    float x3 = __fmul_rn(x2, x);
    float a  = __fadd_rn(x, __fmul_rn(0.044715f, x3));
    float t  = xla_tanhf(__fmul_rn(0.7978845608028654f, a));
    float cdf = __fmul_rn(0.5f, __fadd_rn(1.0f, t));
    return __fmul_rn(x, cdf);
}

__device__ __forceinline__ float bn_exact(float x, float mean, float rstd,
                                          float ga, float be) {
    return __fadd_rn(__fmul_rn(__fmul_rn(__fsub_rn(x, mean), rstd), ga), be);
}

// ---------- Eigen pexp<float> replica ----------
__device__ __forceinline__ float eigen_expf(float x) {
    x = fminf(fmaxf(x, -88.723164f), 88.723164f);
    float m = floorf(__fmaf_rn(x, 1.44269504088896341f, 0.5f));
    float r = __fmaf_rn(m, -0.693359375f, x);
    r = __fmaf_rn(m, 2.12194440e-4f, r);
    float r2 = __fmul_rn(r, r);
    float p = 1.9875691500e-4f;
    p = __fmaf_rn(p, r, 1.3981999507e-3f);
    p = __fmaf_rn(p, r, 8.3334519073e-3f);
    p = __fmaf_rn(p, r, 4.1665795894e-2f);
    p = __fmaf_rn(p, r, 1.6666665459e-1f);
    p = __fmaf_rn(p, r, 5.0000001201e-1f);
    p = __fmaf_rn(p, r2, r);
    p = __fadd_rn(p, 1.0f);
    int mi = (int)m; if (mi < -126) mi = -126; if (mi > 127) mi = 127;
    return __fmul_rn(p, __int_as_float((unsigned)(mi + 127) << 23));
}

// ---------- Eigen plog<float> replica ----------
__device__ __forceinline__ float eigen_logf(float x) {
    int bits = __float_as_int(x);
    float e = (float)(((bits >> 23) & 0xff) - 126);
    float mant = __int_as_float((bits & 0x807fffff) | 0x3f000000);
    if (mant < 0.707106781186547524f) {
        e = __fsub_rn(e, 1.0f);
        mant = __fadd_rn(__fsub_rn(mant, 1.0f), mant);
    } else {
        mant = __fsub_rn(mant, 1.0f);
    }
    float x2 = __fmul_rn(mant, mant);
    float x3 = __fmul_rn(x2, mant);
    float y = 7.0376836292e-2f;
    y = __fmaf_rn(y, mant, -1.1514610310e-1f);
    y = __fmaf_rn(y, mant, 1.1676998740e-1f);
    y = __fmaf_rn(y, mant, -1.2420140846e-1f);
    y = __fmaf_rn(y, mant, 1.4249322787e-1f);
    y = __fmaf_rn(y, mant, -1.6668057665e-1f);
    y = __fmaf_rn(y, mant, 2.0000714765e-1f);
    y = __fmaf_rn(y, mant, -2.4999993993e-1f);
    y = __fmaf_rn(y, mant, 3.3333331174e-1f);
    y = __fmul_rn(y, x3);
    y = __fmaf_rn(e, -2.12194440e-4f, y);
    y = __fsub_rn(y, __fmul_rn(x2, 0.5f));
    float r = __fadd_rn(mant, y);
    return __fmaf_rn(e, 0.693359375f, r);
}

// ---------- pack W = [w1 | wm] ----------
__global__ void kpack(const float* __restrict__ w1, const float* __restrict__ wm) {
    int i = blockIdx.x * 256 + threadIdx.x;
    int c = i / NOUT, k = i - c * NOUT;
    g_W[i] = (k < HC) ? w1[c * HC + k] : wm[c * CC + (k - HC)];
}

// ---------- shared GEMM core: 128(m) x 64(n) block tile ----------
__device__ __forceinline__ void gemm_tile(const float* __restrict__ Ab,
                                          const float* __restrict__ Wb,
                                          int tid, float acc[8][4],
                                          float (*As)[128], float (*Bs)[64]) {
    int mlane = tid & 15;
    int ngrp  = tid >> 4;
#pragma unroll
    for (int i = 0; i < 8; i++)
#pragma unroll
        for (int j = 0; j < 4; j++) acc[i][j] = 0.0f;

    for (int kt = 0; kt < CC; kt += 16) {
#pragma unroll
        for (int i = 0; i < 8; i++) {
            int l = tid + i * 256; int k = l >> 7, mm = l & 127;
            As[k][mm] = Ab[(size_t)(kt + k) * NPTS + mm];
        }
#pragma unroll
        for (int i = 0; i < 4; i++) {
            int l = tid + i * 256; int k = l >> 6, nn = l & 63;
            Bs[k][nn] = Wb[(kt + k) * NOUT + nn];
        }
        __syncthreads();
#pragma unroll
        for (int k = 0; k < 16; k++) {
            float a[8];
#pragma unroll
            for (int i = 0; i < 8; i++) a[i] = As[k][mlane + i * 16];
            float4 b4 = *(const float4*)&Bs[k][ngrp * 4];
#pragma unroll
            for (int i = 0; i < 8; i++) {
                acc[i][0] = __fmaf_rn(a[i], b4.x, acc[i][0]);
                acc[i][1] = __fmaf_rn(a[i], b4.y, acc[i][1]);
                acc[i][2] = __fmaf_rn(a[i], b4.z, acc[i][2]);
                acc[i][3] = __fmaf_rn(a[i], b4.w, acc[i][3]);
            }
        }
        __syncthreads();
    }
}

// ---------- GEMM part Y: cols 0..63 -> g_Y (col-major) + g_Yt (row-major) ----------
__global__ void __launch_bounds__(256) kgemmY(const float* __restrict__ feats) {
    __shared__ float As[16][128];
    __shared__ __align__(16) float Bs[16][64];
    int bm = blockIdx.x;
    int tid = threadIdx.x;
    int b  = bm >> 7;
    int n0 = (bm & 127) << 7;
    const float* Ab = feats + (size_t)b * (CC * NPTS) + n0;
    float acc[8][4];
    gemm_tile(Ab, g_W, tid, acc, As, Bs);
    int mlane = tid & 15, ngrp = tid >> 4;
    int m0 = bm << 7;
#pragma unroll
    for (int i = 0; i < 8; i++) {
        int m = m0 + mlane + i * 16;
#pragma unroll
        for (int j = 0; j < 4; j++)
            g_Y[(size_t)(ngrp * 4 + j) * MTOT + m] = acc[i][j];
        float4 v4 = make_float4(acc[i][0], acc[i][1], acc[i][2], acc[i][3]);
        *(float4*)&g_Yt[(size_t)m * HC + ngrp * 4] = v4;
    }
}

// ---------- GEMM part M: cols 64..319 -> d_out m region (B,256,N) ----------
__global__ void __launch_bounds__(256) kgemmM(const float* __restrict__ feats,
                                              float* __restrict__ out) {
    __shared__ float As[16][128];
    __shared__ __align__(16) float Bs[16][64];
    int bm = blockIdx.x, bn = blockIdx.y;        // bn 0..3
    int tid = threadIdx.x;
    int b  = bm >> 7;
    int n0 = (bm & 127) << 7;
    const float* Ab = feats + (size_t)b * (CC * NPTS) + n0;
    float acc[8][4];
    gemm_tile(Ab, g_W + HC + bn * 64, tid, acc, As, Bs);
    int mlane = tid & 15, ngrp = tid >> 4;
    float* mo = out + OFF_M;
#pragma unroll
    for (int i = 0; i < 8; i++) {
        int n = n0 + mlane + i * 16;
#pragma unroll
        for (int j = 0; j < 4; j++) {
            int d = bn * 64 + ngrp * 4 + j;
            mo[((size_t)(b * CC + d)) * NPTS + n] = acc[i][j];
        }
    }
}

// ---------- L2 prefetch of g_Yt ----------
__global__ void kpref() {
    int i = blockIdx.x * 256 + threadIdx.x;
    float4 v = *(const float4*)&g_Yt[(size_t)i * 4];
    if (v.x == 1.0e38f && v.y == -1.0e38f) g_sink = v.z;
}

// ---------- EXACT y-branch stats: sequential two-pass, software-pipelined ----------
__global__ void __launch_bounds__(64) kstats_y() {
    const int j = threadIdx.x;                 // <<<1, 64>>>
    const float* p = g_Yt + j;
    const int U = 32, NIT = MTOT / U;

    float b0[U], b1[U], b2[U];
    float acc = 0.0f;
#pragma unroll
    for (int u = 0; u < U; u++) b0[u] = p[(size_t)u * HC];
#pragma unroll
    for (int u = 0; u < U; u++) b1[u] = p[(size_t)(U + u) * HC];
    for (int it = 0; it < NIT; it++) {
        if (it + 2 < NIT) {
            const float* q = p + (size_t)(it + 2) * U * HC;
#pragma unroll
            for (int u = 0; u < U; u++) b2[u] = q[(size_t)u * HC];
        }
#pragma unroll
        for (int u = 0; u < U; u++) acc = __fadd_rn(acc, b0[u]);
#pragma unroll
        for (int u = 0; u < U; u++) { b0[u] = b1[u]; b1[u] = b2[u]; }
    }
    float mean = __fdiv_rn(acc, 65536.0f);

    float vac = 0.0f;
#pragma unroll
    for (int u = 0; u < U; u++) b0[u] = p[(size_t)u * HC];
#pragma unroll
    for (int u = 0; u < U; u++) b1[u] = p[(size_t)(U + u) * HC];
    for (int it = 0; it < NIT; it++) {
        if (it + 2 < NIT) {
            const float* q = p + (size_t)(it + 2) * U * HC;
#pragma unroll
            for (int u = 0; u < U; u++) b2[u] = q[(size_t)u * HC];
        }
#pragma unroll
        for (int u = 0; u < U; u++) {
            float d = __fsub_rn(b0[u], mean);
            vac = __fadd_rn(vac, __fmul_rn(d, d));
        }
#pragma unroll
        for (int u = 0; u < U; u++) { b0[u] = b1[u]; b1[u] = b2[u]; }
    }
    float var = __fdiv_rn(vac, 65536.0f);
    g_mean[j] = mean;
    g_rstd[j] = __fdiv_rn(1.0f, __fsqrt_rn(__fadd_rn(var, 1e-5f)));
}

// ---------- merged m-channel stats + gelu(BN) (1e-3 tolerance path) ----------
__global__ void ksum_norm(float* __restrict__ out, const float* __restrict__ gm,
                          const float* __restrict__ bm) {
    int d = blockIdx.x;                     // channel 0..255
    int tid = threadIdx.x;
    __shared__ float s1[256], s2[256];
    float a = 0.0f, q = 0.0f;
    float* mo = out + OFF_M;
    for (int b = 0; b < BB; b++) {
        const float* p = mo + ((size_t)(b * CC + d)) * NPTS;
        for (int i = tid; i < NPTS; i += 256) { float v = p[i]; a += v; q += v * v; }
    }
    s1[tid] = a; s2[tid] = q; __syncthreads();
    for (int s = 128; s > 0; s >>= 1) {
        if (tid < s) { s1[tid] += s1[tid + s]; s2[tid] += s2[tid + s]; }
        __syncthreads();
    }
    __shared__ float s_mean, s_rstd;
    if (tid == 0) {
        float mean = s1[0] * (1.0f / 65536.0f);
        float var  = s2[0] * (1.0f / 65536.0f) - mean * mean;
        s_mean = mean;
        s_rstd = rsqrtf(var + 1e-5f);
        g_mean[HC + d] = mean;
        g_rstd[HC + d] = s_rstd;
    }
    __syncthreads();
    float mean = s_mean, rstd = s_rstd;
    float ga = gm[d], be = bm[d];
    for (int b = 0; b < BB; b++) {
        float4* p = (float4*)(mo + ((size_t)(b * CC + d)) * NPTS);
        for (int i = tid; i < NPTS / 4; i += 256) {
            float4 v = p[i];
            v.x = gelu_fast((v.x - mean) * rstd * ga + be);
            v.y = gelu_fast((v.y - mean) * rstd * ga + be);
            v.z = gelu_fast((v.z - mean) * rstd * ga + be);
            v.w = gelu_fast((v.w - mean) * rstd * ga + be);
            p[i] = v;
        }
    }
}

// ---------- partial h sums (fast path, preds/label only) ----------
__global__ void khpart(const float* __restrict__ g1, const float* __restrict__ b1) {
    int blk = blockIdx.x;
    int tid = threadIdx.x;
    int lane = tid & 31, w = tid >> 5;
    int b = blk >> 6, nc = blk & 63;
    int m0 = b * NPTS + nc * 256;
    for (int jj = 0; jj < 8; jj++) {
        int j = w * 8 + jj;
        float mean = g_mean[j], rstd = g_rstd[j], ga = g1[j], be = b1[j];
        float s = 0.0f;
        for (int c8 = 0; c8 < 8; c8++) {
            float y = g_Y[(size_t)j * MTOT + m0 + c8 * 32 + lane];
            s += gelu_fast((y - mean) * rstd * ga + be);
        }
#pragma unroll
        for (int off = 16; off > 0; off >>= 1) s += __shfl_down_sync(0xffffffffu, s, off);
        if (lane == 0) g_hpart[blk * HC + j] = s;
    }
}

__global__ void klabel(const float* __restrict__ w2, float* __restrict__ out) {
    __shared__ float hsum[BB * HC];
    __shared__ float spred[BB * 10];
    int t = threadIdx.x;
    {
        int bb = t >> 6, j = t & 63;
        float s = 0.0f;
        for (int blk = 0; blk < 64; blk++) s += g_hpart[(bb * 64 + blk) * HC + j];
        hsum[t] = s;
    }
    __syncthreads();
    if (t < BB * 10) {
        int b = t / 10, cl = t - b * 10;
        float p = 0.0f;
        for (int j = 0; j < HC; j++) p += hsum[b * HC + j] * w2[j * 10 + cl];
        p *= (1.0f / 16384.0f);
        spred[t] = p;
        out[OFF_PRED + t] = p;
    }
    __syncthreads();
    if (t < BB) {
        float best = spred[t * 10]; int lab = 0;
        for (int c = 1; c < 10; c++) {
            float v = spred[t * 10 + c];
            if (v > best) { best = v; lab = c; }
        }
        g_label[t] = lab;
    }
}

// ---------- EXACT qh = h @ w2[:,label] ----------
__global__ void kq(const float* __restrict__ g1, const float* __restrict__ b1,
                   const float* __restrict__ w2) {
    int m = blockIdx.x * 256 + threadIdx.x;
    int b = m >> 14;
    int lab = g_label[b];
    float acc = 0.0f;
    for (int j = 0; j < HC; j++) {
        float z = bn_exact(g_Y[(size_t)j * MTOT + m], g_mean[j], g_rstd[j],
                           g1[j], b1[j]);
        acc = __fmaf_rn(gelu_exact(z), w2[j * 10 + lab], acc);
    }
    g_qval[m] = acc;
}

// ---------- log_softmax replication ----------
__global__ void kmax() {
    int b = blockIdx.x, tid = threadIdx.x;
    __shared__ float smax[256];
    const float* qv = g_qval + b * NPTS;
    float mx = -3.402823466e38f;
    for (int i = tid; i < NPTS; i += 256) mx = fmaxf(mx, qv[i]);
    smax[tid] = mx; __syncthreads();
    for (int s = 128; s > 0; s >>= 1) {
        if (tid < s) smax[tid] = fmaxf(smax[tid], smax[tid + s]);
        __syncthreads();
    }
    if (tid == 0) g_max[b] = smax[0];
}

__global__ void kexp() {
    int i = blockIdx.x * 256 + threadIdx.x;
    int b = i >> 14;
    g_exp[i] = eigen_expf(__fsub_rn(g_qval[i], g_max[b]));
}

// serial order-mandated FADD chain, software-pipelined
__global__ void __launch_bounds__(32) kserial() {
    int b = threadIdx.x;
    if (b >= BB) return;
    const float4* e = (const float4*)(g_exp + b * NPTS);
    const int U4 = 8, NIT = NPTS / (U4 * 4);
    float4 b0[U4], b1[U4], b2[U4];
    float acc = 0.0f;
#pragma unroll
    for (int u = 0; u < U4; u++) b0[u] = e[u];
#pragma unroll
    for (int u = 0; u < U4; u++) b1[u] = e[U4 + u];
    for (int it = 0; it < NIT; it++) {
        if (it + 2 < NIT) {
            const float4* q = e + (size_t)(it + 2) * U4;
#pragma unroll
            for (int u = 0; u < U4; u++) b2[u] = q[u];
        }
#pragma unroll
        for (int u = 0; u < U4; u++) {
            acc = __fadd_rn(acc, b0[u].x);
            acc = __fadd_rn(acc, b0[u].y);
            acc = __fadd_rn(acc, b0[u].z);
            acc = __fadd_rn(acc, b0[u].w);
        }
#pragma unroll
        for (int u = 0; u < U4; u++) { b0[u] = b1[u]; b1[u] = b2[u]; }
    }
    g_lse[b] = eigen_logf(acc);
}

// ---------- key precompute: (logp desc, idx asc) packed u64 ----------
__device__ __forceinline__ unsigned long long make_key(float v, int n) {
    unsigned int u = __float_as_uint(v);
    u = (u & 0x80000000u) ? ~u : (u | 0x80000000u);
    return ((unsigned long long)u << 32) | (unsigned int)(16383 - n);
}

__global__ void kkeys() {
    int i = blockIdx.x * 256 + threadIdx.x;   // < 65536
    int b = i >> 14, n = i & 16383;
    float lp = __fsub_rn(__fsub_rn(g_qval[i], g_max[b]), g_lse[b]);
    g_keys[i] = make_key(lp, n);
}

// ---------- top-256 per batch via binary search on keys ----------
__global__ void ktop(const float* __restrict__ points, float* __restrict__ out) {
    int b = blockIdx.x, tid = threadIdx.x;
    int lane = tid & 31;
    __shared__ int stotal;
    __shared__ unsigned long long ssel[NQ];
    __shared__ int scnt;
    const unsigned long long* kv = g_keys + b * NPTS;

    unsigned long long lo = 0ull, hi = 0xFFFFFFFFFFFFFFFFull;
    while (lo < hi) {
        unsigned long long mid = lo + ((hi - lo) >> 1) + 1ull;
        if (tid == 0) stotal = 0;
        __syncthreads();
        int c = 0;
        for (int n = tid; n < NPTS; n += 256)
            c += (kv[n] >= mid) ? 1 : 0;
#pragma unroll
        for (int off = 16; off > 0; off >>= 1) c += __shfl_down_sync(0xffffffffu, c, off);
        if (lane == 0) atomicAdd(&stotal, c);
        __syncthreads();
        int total = stotal;
        __syncthreads();
        if (total >= NQ) lo = mid; else hi = mid - 1ull;
    }
    if (tid == 0) scnt = 0;
    __syncthreads();
    for (int n = tid; n < NPTS; n += 256) {
        unsigned long long key = kv[n];
        if (key >= lo) { int p = atomicAdd(&scnt, 1); ssel[p] = key; }
    }
    __syncthreads();
    for (int k = 2; k <= NQ; k <<= 1) {
        for (int j = k >> 1; j > 0; j >>= 1) {
            int ixj = tid ^ j;
            if (ixj > tid) {
                unsigned long long a = ssel[tid], c = ssel[ixj];
                bool up = ((tid & k) == 0);
                if ((a > c) == up) { ssel[tid] = c; ssel[ixj] = a; }
            }
            __syncthreads();
        }
    }
    unsigned long long key = ssel[255 - tid];
    int n = 16383 - (int)(unsigned int)(key & 0xFFFFFFFFull);
    g_qidx[b * NQ + tid] = n;
    for (int c = 0; c < 3; c++)
        out[OFF_QUERY + (b * 3 + c) * NQ + tid] =
            points[(size_t)(b * 3 + c) * NPTS + n];
}

__global__ void kgather(const float* __restrict__ feats, float* __restrict__ out) {
    int bc = blockIdx.x;
    int r = threadIdx.x;
    int b = bc >> 8;
    int n = g_qidx[b * NQ + r];
    out[OFF_QF + (size_t)bc * NQ + r] = feats[(size_t)bc * NPTS + n];
}

__global__ void kball(const float* __restrict__ points, float* __restrict__ out) {
    int tid = threadIdx.x;
    int lane = tid & 31;
    int gw = blockIdx.x * 8 + (tid >> 5);
    int b = gw >> 8;
    int nq = g_qidx[gw];
    const float* px = points + (size_t)b * 3 * NPTS;
    float qx = px[nq], qy = px[NPTS + nq], qz = px[2 * NPTS + nq];
    float* o1 = out + OFF_G1 + (size_t)gw * NS1;
    float* o0 = out + OFF_G0 + (size_t)gw * NS0;
    const float R0 = 0.04000000283122062f;
    const float R1 = 0.16000001132488251f;
    int cnt0 = 0, cnt1 = 0, first0 = -1, first1 = -1;
    for (int base = 0; base < NPTS; base += 32) {
        if (cnt0 >= NS0 && cnt1 >= NS1) break;
        int i = base + lane;
        float dx = px[i] - qx;
        float dy = px[NPTS + i] - qy;
        float dz = px[2 * NPTS + i] - qz;
        float sq = __fadd_rn(__fadd_rn(__fmul_rn(dx, dx), __fmul_rn(dy, dy)),
                             __fmul_rn(dz, dz));
        bool in1 = (sq <= R1), in0 = (sq <= R0);
        unsigned m1 = __ballot_sync(0xffffffffu, in1);
        unsigned m0 = __ballot_sync(0xffffffffu, in0);
        unsigned ltm = (lane == 31) ? 0x7fffffffu : ((1u << lane) - 1u);
        if (in1) { int s = cnt1 + __popc(m1 & ltm); if (s < NS1) o1[s] = (float)i; }
        if (in0) { int s = cnt0 + __popc(m0 & ltm); if (s < NS0) o0[s] = (float)i; }
        if (first1 < 0 && m1) first1 = base + __ffs((int)m1) - 1;
        if (first0 < 0 && m0) first0 = base + __ffs((int)m0) - 1;
        cnt1 += __popc(m1); cnt0 += __popc(m0);
    }
    float f1 = (first1 >= 0) ? (float)first1 : (float)(NPTS - 1);
    float f0 = (first0 >= 0) ? (float)first0 : (float)(NPTS - 1);
    for (int s = lane; s < NS1; s += 32) if (s >= cnt1) o1[s] = f1;
    for (int s = lane; s < NS0; s += 32) if (s >= cnt0) o0[s] = f0;
}

extern "C" void kernel_launch(void* const* d_in, const int* in_sizes, int n_in,
                              void* d_out, int out_size) {
    const float* points = (const float*)d_in[0];
    const float* feats  = (const float*)d_in[1];
    const float* w1 = (const float*)d_in[2];
    const float* g1 = (const float*)d_in[3];
    const float* b1 = (const float*)d_in[4];
    const float* w2 = (const float*)d_in[5];
    const float* wm = (const float*)d_in[6];
    const float* gm = (const float*)d_in[7];
    const float* bm = (const float*)d_in[8];
    float* out = (float*)d_out;

    // fork-join resources (created per call; never destroyed mid-capture)
    cudaStream_t s2;
    cudaEvent_t evA, evB;
    cudaStreamCreateWithFlags(&s2, cudaStreamNonBlocking);
    cudaEventCreateWithFlags(&evA, cudaEventDisableTiming);
    cudaEventCreateWithFlags(&evB, cudaEventDisableTiming);

    kpack<<<320, 256>>>(w1, wm);
    kgemmY<<<512, 256>>>(feats);

    // fork: side stream computes exact y-stats while main stream does m-branch
    cudaEventRecord(evA, 0);
    cudaStreamWaitEvent(s2, evA, 0);
    kpref<<<4096, 256, 0, s2>>>();
    kstats_y<<<1, 64, 0, s2>>>();
    cudaEventRecord(evB, s2);

    kgemmM<<<dim3(512, 4), 256>>>(feats, out);
    ksum_norm<<<256, 256>>>(out, gm, bm);

    // join
    cudaStreamWaitEvent(0, evB, 0);

    khpart<<<256, 256>>>(g1, b1);
    klabel<<<1, 256>>>(w2, out);
    kq<<<256, 256>>>(g1, b1, w2);
    kmax<<<4, 256>>>();
    kexp<<<256, 256>>>();
    kserial<<<1, 32>>>();
    kkeys<<<256, 256>>>();
    ktop<<<4, 256>>>(points, out);
    kgather<<<1024, 256>>>(feats, out);
    kball<<<128, 256>>>(points, out);
}

// round 14
// speedup vs baseline: 2.0108x; 2.0108x over previous
#include <cuda_runtime.h>
#include <cstdint>
#include <math.h>

#define BB 4
#define CC 256
#define NPTS 16384
#define MTOT 65536
#define HC 64
#define NOUT 320
#define NQ 256
#define NS0 32
#define NS1 64

#define OFF_QUERY 0
#define OFF_QF    3072
#define OFF_PRED  265216
#define OFF_M     265256
#define OFF_G0    17042472
#define OFF_G1    17075240

__device__ float g_W[CC * NOUT];
__device__ float g_Y[HC * MTOT];    // column-major [col][m]  (for kq/khpart)
__device__ float g_Yt[MTOT * HC];   // row-major [m][col]     (for exact stats)
__device__ float g_mean[NOUT];
__device__ float g_rstd[NOUT];
__device__ float g_hpart[256 * HC];
__device__ int   g_label[BB];
__device__ float g_qval[MTOT];
__device__ float g_exp[MTOT];
__device__ unsigned long long g_keys[MTOT];
__device__ float g_max[BB];
__device__ float g_lse[BB];
__device__ int   g_qidx[BB * NQ];

#define CP_A16(daddr, gptr) \
    asm volatile("cp.async.cg.shared.global [%0], [%1], 16;" :: "r"(daddr), "l"(gptr) : "memory")
#define CP_COMMIT() asm volatile("cp.async.commit_group;" ::: "memory")
#define CP_WAIT1()  asm volatile("cp.async.wait_group 1;" ::: "memory")
#define CP_WAIT0()  asm volatile("cp.async.wait_group 0;" ::: "memory")

// ---------- fast gelu (1e-3-tolerance outputs only) ----------
__device__ __forceinline__ float gelu_fast(float x) {
    float x3 = x * x * x;
    float t = tanhf(0.7978845608028654f * (x + 0.044715f * x3));
    return 0.5f * x * (1.0f + t);
}

// ---------- XLA FastTanh (rational, separate mul/add, fdiv) ----------
__device__ __forceinline__ float xla_tanhf(float x) {
    if (fabsf(x) < 0.0004f) return x;
    float xc = fminf(fmaxf(x, -7.90531110763549805f), 7.90531110763549805f);
    float x2 = __fmul_rn(xc, xc);
    float p = -2.76076847742355e-16f;
    p = __fadd_rn(__fmul_rn(p, x2), 2.00018790482477e-13f);
    p = __fadd_rn(__fmul_rn(p, x2), -8.60467152213735e-11f);
    p = __fadd_rn(__fmul_rn(p, x2), 5.12229709037114e-08f);
    p = __fadd_rn(__fmul_rn(p, x2), 1.48572235717979e-05f);
    p = __fadd_rn(__fmul_rn(p, x2), 6.37261928875436e-04f);
    p = __fadd_rn(__fmul_rn(p, x2), 4.89352455891786e-03f);
    float num = __fmul_rn(xc, p);
    float q = 1.19825839466702e-06f;
    q = __fadd_rn(__fmul_rn(q, x2), 1.18534705686654e-04f);
    q = __fadd_rn(__fmul_rn(q, x2), 2.26843463243900e-03f);
    q = __fadd_rn(__fmul_rn(q, x2), 4.89352518554385e-03f);
    return __fdiv_rn(num, q);
}

__device__ __forceinline__ float gelu_exact(float x) {
    float x2 = __fmul_rn(x, x);
    float x3 = __fmul_rn(x2, x);
    float a  = __fadd_rn(x, __fmul_rn(0.044715f, x3));
    float t  = xla_tanhf(__fmul_rn(0.7978845608028654f, a));
    float cdf = __fmul_rn(0.5f, __fadd_rn(1.0f, t));
    return __fmul_rn(x, cdf);
}

__device__ __forceinline__ float bn_exact(float x, float mean, float rstd,
                                          float ga, float be) {
    return __fadd_rn(__fmul_rn(__fmul_rn(__fsub_rn(x, mean), rstd), ga), be);
}

// ---------- Eigen pexp<float> replica ----------
__device__ __forceinline__ float eigen_expf(float x) {
    x = fminf(fmaxf(x, -88.723164f), 88.723164f);
    float m = floorf(__fmaf_rn(x, 1.44269504088896341f, 0.5f));
    float r = __fmaf_rn(m, -0.693359375f, x);
    r = __fmaf_rn(m, 2.12194440e-4f, r);
    float r2 = __fmul_rn(r, r);
    float p = 1.9875691500e-4f;
    p = __fmaf_rn(p, r, 1.3981999507e-3f);
    p = __fmaf_rn(p, r, 8.3334519073e-3f);
    p = __fmaf_rn(p, r, 4.1665795894e-2f);
    p = __fmaf_rn(p, r, 1.6666665459e-1f);
    p = __fmaf_rn(p, r, 5.0000001201e-1f);
    p = __fmaf_rn(p, r2, r);
    p = __fadd_rn(p, 1.0f);
    int mi = (int)m; if (mi < -126) mi = -126; if (mi > 127) mi = 127;
    return __fmul_rn(p, __int_as_float((unsigned)(mi + 127) << 23));
}

// ---------- Eigen plog<float> replica ----------
__device__ __forceinline__ float eigen_logf(float x) {
    int bits = __float_as_int(x);
    float e = (float)(((bits >> 23) & 0xff) - 126);
    float mant = __int_as_float((bits & 0x807fffff) | 0x3f000000);
    if (mant < 0.707106781186547524f) {
        e = __fsub_rn(e, 1.0f);
        mant = __fadd_rn(__fsub_rn(mant, 1.0f), mant);
    } else {
        mant = __fsub_rn(mant, 1.0f);
    }
    float x2 = __fmul_rn(mant, mant);
    float x3 = __fmul_rn(x2, mant);
    float y = 7.0376836292e-2f;
    y = __fmaf_rn(y, mant, -1.1514610310e-1f);
    y = __fmaf_rn(y, mant, 1.1676998740e-1f);
    y = __fmaf_rn(y, mant, -1.2420140846e-1f);
    y = __fmaf_rn(y, mant, 1.4249322787e-1f);
    y = __fmaf_rn(y, mant, -1.6668057665e-1f);
    y = __fmaf_rn(y, mant, 2.0000714765e-1f);
    y = __fmaf_rn(y, mant, -2.4999993993e-1f);
    y = __fmaf_rn(y, mant, 3.3333331174e-1f);
    y = __fmul_rn(y, x3);
    y = __fmaf_rn(e, -2.12194440e-4f, y);
    y = __fsub_rn(y, __fmul_rn(x2, 0.5f));
    float r = __fadd_rn(mant, y);
    return __fmaf_rn(e, 0.693359375f, r);
}

// ---------- pack W = [w1 | wm] ----------
__global__ void kpack(const float* __restrict__ w1, const float* __restrict__ wm) {
    int i = blockIdx.x * 256 + threadIdx.x;
    int c = i / NOUT, k = i - c * NOUT;
    g_W[i] = (k < HC) ? w1[c * HC + k] : wm[c * CC + (k - HC)];
}

// ---------- shared GEMM core: 128(m) x 64(n) block tile ----------
__device__ __forceinline__ void gemm_tile(const float* __restrict__ Ab,
                                          const float* __restrict__ Wb,
                                          int tid, float acc[8][4],
                                          float (*As)[128], float (*Bs)[64]) {
    int mlane = tid & 15;
    int ngrp  = tid >> 4;
#pragma unroll
    for (int i = 0; i < 8; i++)
#pragma unroll
        for (int j = 0; j < 4; j++) acc[i][j] = 0.0f;

    for (int kt = 0; kt < CC; kt += 16) {
#pragma unroll
        for (int i = 0; i < 8; i++) {
            int l = tid + i * 256; int k = l >> 7, mm = l & 127;
            As[k][mm] = Ab[(size_t)(kt + k) * NPTS + mm];
        }
#pragma unroll
        for (int i = 0; i < 4; i++) {
            int l = tid + i * 256; int k = l >> 6, nn = l & 63;
            Bs[k][nn] = Wb[(kt + k) * NOUT + nn];
        }
        __syncthreads();
#pragma unroll
        for (int k = 0; k < 16; k++) {
            float a[8];
#pragma unroll
            for (int i = 0; i < 8; i++) a[i] = As[k][mlane + i * 16];
            float4 b4 = *(const float4*)&Bs[k][ngrp * 4];
#pragma unroll
            for (int i = 0; i < 8; i++) {
                acc[i][0] = __fmaf_rn(a[i], b4.x, acc[i][0]);
                acc[i][1] = __fmaf_rn(a[i], b4.y, acc[i][1]);
                acc[i][2] = __fmaf_rn(a[i], b4.z, acc[i][2]);
                acc[i][3] = __fmaf_rn(a[i], b4.w, acc[i][3]);
            }
        }
        __syncthreads();
    }
}

// ---------- GEMM part Y: cols 0..63 -> g_Y (col-major) + g_Yt (row-major) ----------
__global__ void __launch_bounds__(256) kgemmY(const float* __restrict__ feats) {
    __shared__ float As[16][128];
    __shared__ __align__(16) float Bs[16][64];
    int bm = blockIdx.x;
    int tid = threadIdx.x;
    int b  = bm >> 7;
    int n0 = (bm & 127) << 7;
    const float* Ab = feats + (size_t)b * (CC * NPTS) + n0;
    float acc[8][4];
    gemm_tile(Ab, g_W, tid, acc, As, Bs);
    int mlane = tid & 15, ngrp = tid >> 4;
    int m0 = bm << 7;
#pragma unroll
    for (int i = 0; i < 8; i++) {
        int m = m0 + mlane + i * 16;
#pragma unroll
        for (int j = 0; j < 4; j++)
            g_Y[(size_t)(ngrp * 4 + j) * MTOT + m] = acc[i][j];
        float4 v4 = make_float4(acc[i][0], acc[i][1], acc[i][2], acc[i][3]);
        *(float4*)&g_Yt[(size_t)m * HC + ngrp * 4] = v4;
    }
}

// ---------- GEMM part M: cols 64..319 -> d_out m region (B,256,N) ----------
__global__ void __launch_bounds__(256) kgemmM(const float* __restrict__ feats,
                                              float* __restrict__ out) {
    __shared__ float As[16][128];
    __shared__ __align__(16) float Bs[16][64];
    int bm = blockIdx.x, bn = blockIdx.y;        // bn 0..3
    int tid = threadIdx.x;
    int b  = bm >> 7;
    int n0 = (bm & 127) << 7;
    const float* Ab = feats + (size_t)b * (CC * NPTS) + n0;
    float acc[8][4];
    gemm_tile(Ab, g_W + HC + bn * 64, tid, acc, As, Bs);
    int mlane = tid & 15, ngrp = tid >> 4;
    float* mo = out + OFF_M;
#pragma unroll
    for (int i = 0; i < 8; i++) {
        int n = n0 + mlane + i * 16;
#pragma unroll
        for (int j = 0; j < 4; j++) {
            int d = bn * 64 + ngrp * 4 + j;
            mo[((size_t)(b * CC + d)) * NPTS + n] = acc[i][j];
        }
    }
}

// ---------- EXACT y-branch stats: producer/consumer smem ring (latency-immune) ----
// 2 consumer warps (tid<64): per-channel sequential FADD chains out of smem.
// 6 producer warps: cp.async stream g_Yt into 3-buffer ring, 2 stages ahead.
// Summation order identical to ascending-i sequential loop -> bit-exact.
__global__ void __launch_bounds__(256) kstats_y() {
    __shared__ float sm[3][64][64];            // 48 KB ring, 64 rows/stage
    const int tid = threadIdx.x;
    const int NST = MTOT / 64;                 // 1024 stages
    const bool cons = tid < 64;
    const int j = tid;

    auto fill = [&](int s) {
        int pb = s % 3;
        const float* gb = g_Yt + (size_t)s * 64 * HC;
        for (int t = tid - 64; t < 1024; t += 192) {
            int row = t >> 4, c4 = t & 15;
            uint32_t da = (uint32_t)__cvta_generic_to_shared(&sm[pb][row][c4 * 4]);
            CP_A16(da, gb + (size_t)row * HC + c4 * 4);
        }
        CP_COMMIT();
    };

    // ================= pass 1: mean =================
    float acc = 0.0f;
    if (!cons) { fill(0); fill(1); }
    for (int s = 0; s < NST; s++) {
        if (!cons) CP_WAIT1();                 // stage s guaranteed landed
        __syncthreads();
        if (cons) {
            const float* buf = &sm[s % 3][0][j];
#pragma unroll
            for (int r = 0; r < 64; r++)
                acc = __fadd_rn(acc, buf[r * 64]);
        } else {
            if (s + 2 < NST) fill(s + 2); else CP_COMMIT();
        }
    }
    float mean = cons ? __fdiv_rn(acc, 65536.0f) : 0.0f;
    if (!cons) CP_WAIT0();
    __syncthreads();

    // ================= pass 2: var =================
    float vac = 0.0f;
    if (!cons) { fill(0); fill(1); }
    for (int s = 0; s < NST; s++) {
        if (!cons) CP_WAIT1();
        __syncthreads();
        if (cons) {
            const float* buf = &sm[s % 3][0][j];
#pragma unroll
            for (int r = 0; r < 64; r++) {
                float d = __fsub_rn(buf[r * 64], mean);
                vac = __fadd_rn(vac, __fmul_rn(d, d));
            }
        } else {
            if (s + 2 < NST) fill(s + 2); else CP_COMMIT();
        }
    }
    if (cons) {
        float var = __fdiv_rn(vac, 65536.0f);
        g_mean[j] = mean;
        g_rstd[j] = __fdiv_rn(1.0f, __fsqrt_rn(__fadd_rn(var, 1e-5f)));
    }
}

// ---------- merged m-channel stats + gelu(BN) (1e-3 tolerance path) ----------
__global__ void ksum_norm(float* __restrict__ out, const float* __restrict__ gm,
                          const float* __restrict__ bm) {
    int d = blockIdx.x;                     // channel 0..255
    int tid = threadIdx.x;
    __shared__ float s1[256], s2[256];
    float a = 0.0f, q = 0.0f;
    float* mo = out + OFF_M;
    for (int b = 0; b < BB; b++) {
        const float* p = mo + ((size_t)(b * CC + d)) * NPTS;
        for (int i = tid; i < NPTS; i += 256) { float v = p[i]; a += v; q += v * v; }
    }
    s1[tid] = a; s2[tid] = q; __syncthreads();
    for (int s = 128; s > 0; s >>= 1) {
        if (tid < s) { s1[tid] += s1[tid + s]; s2[tid] += s2[tid + s]; }
        __syncthreads();
    }
    __shared__ float s_mean, s_rstd;
    if (tid == 0) {
        float mean = s1[0] * (1.0f / 65536.0f);
        float var  = s2[0] * (1.0f / 65536.0f) - mean * mean;
        s_mean = mean;
        s_rstd = rsqrtf(var + 1e-5f);
        g_mean[HC + d] = mean;
        g_rstd[HC + d] = s_rstd;
    }
    __syncthreads();
    float mean = s_mean, rstd = s_rstd;
    float ga = gm[d], be = bm[d];
    for (int b = 0; b < BB; b++) {
        float4* p = (float4*)(mo + ((size_t)(b * CC + d)) * NPTS);
        for (int i = tid; i < NPTS / 4; i += 256) {
            float4 v = p[i];
            v.x = gelu_fast((v.x - mean) * rstd * ga + be);
            v.y = gelu_fast((v.y - mean) * rstd * ga + be);
            v.z = gelu_fast((v.z - mean) * rstd * ga + be);
            v.w = gelu_fast((v.w - mean) * rstd * ga + be);
            p[i] = v;
        }
    }
}

// ---------- partial h sums (fast path, preds/label only) ----------
__global__ void khpart(const float* __restrict__ g1, const float* __restrict__ b1) {
    int blk = blockIdx.x;
    int tid = threadIdx.x;
    int lane = tid & 31, w = tid >> 5;
    int b = blk >> 6, nc = blk & 63;
    int m0 = b * NPTS + nc * 256;
    for (int jj = 0; jj < 8; jj++) {
        int j = w * 8 + jj;
        float mean = g_mean[j], rstd = g_rstd[j], ga = g1[j], be = b1[j];
        float s = 0.0f;
        for (int c8 = 0; c8 < 8; c8++) {
            float y = g_Y[(size_t)j * MTOT + m0 + c8 * 32 + lane];
            s += gelu_fast((y - mean) * rstd * ga + be);
        }
#pragma unroll
        for (int off = 16; off > 0; off >>= 1) s += __shfl_down_sync(0xffffffffu, s, off);
        if (lane == 0) g_hpart[blk * HC + j] = s;
    }
}

__global__ void klabel(const float* __restrict__ w2, float* __restrict__ out) {
    __shared__ float hsum[BB * HC];
    __shared__ float spred[BB * 10];
    int t = threadIdx.x;
    {
        int bb = t >> 6, j = t & 63;
        float s = 0.0f;
        for (int blk = 0; blk < 64; blk++) s += g_hpart[(bb * 64 + blk) * HC + j];
        hsum[t] = s;
    }
    __syncthreads();
    if (t < BB * 10) {
        int b = t / 10, cl = t - b * 10;
        float p = 0.0f;
        for (int j = 0; j < HC; j++) p += hsum[b * HC + j] * w2[j * 10 + cl];
        p *= (1.0f / 16384.0f);
        spred[t] = p;
        out[OFF_PRED + t] = p;
    }
    __syncthreads();
    if (t < BB) {
        float best = spred[t * 10]; int lab = 0;
        for (int c = 1; c < 10; c++) {
            float v = spred[t * 10 + c];
            if (v > best) { best = v; lab = c; }
        }
        g_label[t] = lab;
    }
}

// ---------- EXACT qh = h @ w2[:,label] ----------
__global__ void kq(const float* __restrict__ g1, const float* __restrict__ b1,
                   const float* __restrict__ w2) {
    int m = blockIdx.x * 256 + threadIdx.x;
    int b = m >> 14;
    int lab = g_label[b];
    float acc = 0.0f;
    for (int j = 0; j < HC; j++) {
        float z = bn_exact(g_Y[(size_t)j * MTOT + m], g_mean[j], g_rstd[j],
                           g1[j], b1[j]);
        acc = __fmaf_rn(gelu_exact(z), w2[j * 10 + lab], acc);
    }
    g_qval[m] = acc;
}

// ---------- log_softmax replication ----------
__global__ void kmax() {
    int b = blockIdx.x, tid = threadIdx.x;
    __shared__ float smax[256];
    const float* qv = g_qval + b * NPTS;
    float mx = -3.402823466e38f;
    for (int i = tid; i < NPTS; i += 256) mx = fmaxf(mx, qv[i]);
    smax[tid] = mx; __syncthreads();
    for (int s = 128; s > 0; s >>= 1) {
        if (tid < s) smax[tid] = fmaxf(smax[tid], smax[tid + s]);
        __syncthreads();
    }
    if (tid == 0) g_max[b] = smax[0];
}

__global__ void kexp() {
    int i = blockIdx.x * 256 + threadIdx.x;
    int b = i >> 14;
    g_exp[i] = eigen_expf(__fsub_rn(g_qval[i], g_max[b]));
}

// serial order-mandated FADD chain, software-pipelined
__global__ void __launch_bounds__(32) kserial() {
    int b = threadIdx.x;
    if (b >= BB) return;
    const float4* e = (const float4*)(g_exp + b * NPTS);
    const int U4 = 8, NIT = NPTS / (U4 * 4);
    float4 b0[U4], b1[U4], b2[U4];
    float acc = 0.0f;
#pragma unroll
    for (int u = 0; u < U4; u++) b0[u] = e[u];
#pragma unroll
    for (int u = 0; u < U4; u++) b1[u] = e[U4 + u];
    for (int it = 0; it < NIT; it++) {
        if (it + 2 < NIT) {
            const float4* q = e + (size_t)(it + 2) * U4;
#pragma unroll
            for (int u = 0; u < U4; u++) b2[u] = q[u];
        }
#pragma unroll
        for (int u = 0; u < U4; u++) {
            acc = __fadd_rn(acc, b0[u].x);
            acc = __fadd_rn(acc, b0[u].y);
            acc = __fadd_rn(acc, b0[u].z);
            acc = __fadd_rn(acc, b0[u].w);
        }
#pragma unroll
        for (int u = 0; u < U4; u++) { b0[u] = b1[u]; b1[u] = b2[u]; }
    }
    g_lse[b] = eigen_logf(acc);
}

// ---------- key precompute: (logp desc, idx asc) packed u64 ----------
__device__ __forceinline__ unsigned long long make_key(float v, int n) {
    unsigned int u = __float_as_uint(v);
    u = (u & 0x80000000u) ? ~u : (u | 0x80000000u);
    return ((unsigned long long)u << 32) | (unsigned int)(16383 - n);
}

__global__ void kkeys() {
    int i = blockIdx.x * 256 + threadIdx.x;   // < 65536
    int b = i >> 14, n = i & 16383;
    float lp = __fsub_rn(__fsub_rn(g_qval[i], g_max[b]), g_lse[b]);
    g_keys[i] = make_key(lp, n);
}

// ---------- top-256 per batch via binary search on keys ----------
__global__ void ktop(const float* __restrict__ points, float* __restrict__ out) {
    int b = blockIdx.x, tid = threadIdx.x;
    int lane = tid & 31;
    __shared__ int stotal;
    __shared__ unsigned long long ssel[NQ];
    __shared__ int scnt;
    const unsigned long long* kv = g_keys + b * NPTS;

    unsigned long long lo = 0ull, hi = 0xFFFFFFFFFFFFFFFFull;
    while (lo < hi) {
        unsigned long long mid = lo + ((hi - lo) >> 1) + 1ull;
        if (tid == 0) stotal = 0;
        __syncthreads();
        int c = 0;
        for (int n = tid; n < NPTS; n += 256)
            c += (kv[n] >= mid) ? 1 : 0;
#pragma unroll
        for (int off = 16; off > 0; off >>= 1) c += __shfl_down_sync(0xffffffffu, c, off);
        if (lane == 0) atomicAdd(&stotal, c);
        __syncthreads();
        int total = stotal;
        __syncthreads();
        if (total >= NQ) lo = mid; else hi = mid - 1ull;
    }
    if (tid == 0) scnt = 0;
    __syncthreads();
    for (int n = tid; n < NPTS; n += 256) {
        unsigned long long key = kv[n];
        if (key >= lo) { int p = atomicAdd(&scnt, 1); ssel[p] = key; }
    }
    __syncthreads();
    for (int k = 2; k <= NQ; k <<= 1) {
        for (int j = k >> 1; j > 0; j >>= 1) {
            int ixj = tid ^ j;
            if (ixj > tid) {
                unsigned long long a = ssel[tid], c = ssel[ixj];
                bool up = ((tid & k) == 0);
                if ((a > c) == up) { ssel[tid] = c; ssel[ixj] = a; }
            }
            __syncthreads();
        }
    }
    unsigned long long key = ssel[255 - tid];
    int n = 16383 - (int)(unsigned int)(key & 0xFFFFFFFFull);
    g_qidx[b * NQ + tid] = n;
    for (int c = 0; c < 3; c++)
        out[OFF_QUERY + (b * 3 + c) * NQ + tid] =
            points[(size_t)(b * 3 + c) * NPTS + n];
}

__global__ void kgather(const float* __restrict__ feats, float* __restrict__ out) {
    int bc = blockIdx.x;
    int r = threadIdx.x;
    int b = bc >> 8;
    int n = g_qidx[b * NQ + r];
    out[OFF_QF + (size_t)bc * NQ + r] = feats[(size_t)bc * NPTS + n];
}

__global__ void kball(const float* __restrict__ points, float* __restrict__ out) {
    int tid = threadIdx.x;
    int lane = tid & 31;
    int gw = blockIdx.x * 8 + (tid >> 5);
    int b = gw >> 8;
    int nq = g_qidx[gw];
    const float* px = points + (size_t)b * 3 * NPTS;
    float qx = px[nq], qy = px[NPTS + nq], qz = px[2 * NPTS + nq];
    float* o1 = out + OFF_G1 + (size_t)gw * NS1;
    float* o0 = out + OFF_G0 + (size_t)gw * NS0;
    const float R0 = 0.04000000283122062f;
    const float R1 = 0.16000001132488251f;
    int cnt0 = 0, cnt1 = 0, first0 = -1, first1 = -1;
    for (int base = 0; base < NPTS; base += 32) {
        if (cnt0 >= NS0 && cnt1 >= NS1) break;
        int i = base + lane;
        float dx = px[i] - qx;
        float dy = px[NPTS + i] - qy;
        float dz = px[2 * NPTS + i] - qz;
        float sq = __fadd_rn(__fadd_rn(__fmul_rn(dx, dx), __fmul_rn(dy, dy)),
                             __fmul_rn(dz, dz));
        bool in1 = (sq <= R1), in0 = (sq <= R0);
        unsigned m1 = __ballot_sync(0xffffffffu, in1);
        unsigned m0 = __ballot_sync(0xffffffffu, in0);
        unsigned ltm = (lane == 31) ? 0x7fffffffu : ((1u << lane) - 1u);
        if (in1) { int s = cnt1 + __popc(m1 & ltm); if (s < NS1) o1[s] = (float)i; }
        if (in0) { int s = cnt0 + __popc(m0 & ltm); if (s < NS0) o0[s] = (float)i; }
        if (first1 < 0 && m1) first1 = base + __ffs((int)m1) - 1;
        if (first0 < 0 && m0) first0 = base + __ffs((int)m0) - 1;
        cnt1 += __popc(m1); cnt0 += __popc(m0);
    }
    float f1 = (first1 >= 0) ? (float)first1 : (float)(NPTS - 1);
    float f0 = (first0 >= 0) ? (float)first0 : (float)(NPTS - 1);
    for (int s = lane; s < NS1; s += 32) if (s >= cnt1) o1[s] = f1;
    for (int s = lane; s < NS0; s += 32) if (s >= cnt0) o0[s] = f0;
}

extern "C" void kernel_launch(void* const* d_in, const int* in_sizes, int n_in,
                              void* d_out, int out_size) {
    const float* points = (const float*)d_in[0];
    const float* feats  = (const float*)d_in[1];
    const float* w1 = (const float*)d_in[2];
    const float* g1 = (const float*)d_in[3];
    const float* b1 = (const float*)d_in[4];
    const float* w2 = (const float*)d_in[5];
    const float* wm = (const float*)d_in[6];
    const float* gm = (const float*)d_in[7];
    const float* bm = (const float*)d_in[8];
    float* out = (float*)d_out;

    cudaStream_t s2;
    cudaEvent_t evA, evB;
    cudaStreamCreateWithFlags(&s2, cudaStreamNonBlocking);
    cudaEventCreateWithFlags(&evA, cudaEventDisableTiming);
    cudaEventCreateWithFlags(&evB, cudaEventDisableTiming);

    kpack<<<320, 256>>>(w1, wm);
    kgemmY<<<512, 256>>>(feats);

    // fork: latency-immune exact y-stats alongside the m-branch GEMM
    cudaEventRecord(evA, 0);
    cudaStreamWaitEvent(s2, evA, 0);
    kstats_y<<<1, 256, 0, s2>>>();
    cudaEventRecord(evB, s2);

    kgemmM<<<dim3(512, 4), 256>>>(feats, out);
    ksum_norm<<<256, 256>>>(out, gm, bm);

    // join
    cudaStreamWaitEvent(0, evB, 0);

    khpart<<<256, 256>>>(g1, b1);
    klabel<<<1, 256>>>(w2, out);
    kq<<<256, 256>>>(g1, b1, w2);
    kmax<<<4, 256>>>();
    kexp<<<256, 256>>>();
    kserial<<<1, 32>>>();
    kkeys<<<256, 256>>>();
    ktop<<<4, 256>>>(points, out);
    kgather<<<1024, 256>>>(feats, out);
    kball<<<128, 256>>>(points, out);
}